// round 2
// baseline (speedup 1.0000x reference)
#include <cuda_runtime.h>
#include <cuda_bf16.h>
#include <cstddef>

// Problem constants
#define NN   50000
#define EE   800000
#define KIN  512
#define HO   256    // H*OUT
#define NH   8
#define CC   16

// ---------------- scratch (static device globals; no allocation) ----------------
__device__ __align__(16) float g_h1[(size_t)NN * HO];    // x @ W1
__device__ __align__(16) float g_out1[(size_t)NN * HO];  // layer-1 output (post ELU)
__device__ __align__(16) float g_es1[NN * NH];
__device__ __align__(16) float g_ed1[NN * NH];
__device__ __align__(16) float g_h2[NN * CC];            // out1 @ W2
__device__ float g_es2[NN];
__device__ float g_ed2[NN];
__device__ int   g_deg[NN];
__device__ int   g_rowptr[NN + 1];
__device__ int   g_cursor[NN];
__device__ int   g_csrsrc[EE];

// ---------------- GEMM1: h1 = x[N,512] @ W1[512,256] ----------------
// 64x64 block tile, 16 k-tile, 256 threads, 4x4 microtile.
__global__ __launch_bounds__(256) void gemm1_kernel(const float* __restrict__ A,
                                                    const float* __restrict__ B) {
    __shared__ float As[16][68];   // padded, stored transposed [k][m]
    __shared__ float Bs[16][64];   // [k][n]

    int tid = threadIdx.x;
    int bm = blockIdx.y * 64;
    int bn = blockIdx.x * 64;

    int aRow = tid >> 2;            // 0..63
    int aCol = (tid & 3) << 2;      // 0,4,8,12
    int bRow = tid >> 4;            // 0..15
    int bCol = (tid & 15) << 2;     // 0..60

    int ty = tid >> 4;              // 0..15
    int tx = tid & 15;              // 0..15

    float creg[4][4];
#pragma unroll
    for (int i = 0; i < 4; i++)
#pragma unroll
        for (int j = 0; j < 4; j++) creg[i][j] = 0.0f;

    bool aValid = (bm + aRow) < NN;
    const float* Aptr = A + (size_t)(bm + aRow) * KIN + aCol;

    for (int k0 = 0; k0 < KIN; k0 += 16) {
        float4 av = aValid ? *(const float4*)(Aptr + k0) : make_float4(0.f, 0.f, 0.f, 0.f);
        float4 bv = *(const float4*)(B + (size_t)(k0 + bRow) * HO + bn + bCol);

        As[aCol + 0][aRow] = av.x;
        As[aCol + 1][aRow] = av.y;
        As[aCol + 2][aRow] = av.z;
        As[aCol + 3][aRow] = av.w;
        *(float4*)&Bs[bRow][bCol] = bv;
        __syncthreads();

#pragma unroll
        for (int k = 0; k < 16; k++) {
            float4 a4 = *(const float4*)&As[k][ty << 2];
            float4 b4 = *(const float4*)&Bs[k][tx << 2];
            float ar[4] = {a4.x, a4.y, a4.z, a4.w};
            float br[4] = {b4.x, b4.y, b4.z, b4.w};
#pragma unroll
            for (int i = 0; i < 4; i++)
#pragma unroll
                for (int j = 0; j < 4; j++)
                    creg[i][j] = fmaf(ar[i], br[j], creg[i][j]);
        }
        __syncthreads();
    }

#pragma unroll
    for (int i = 0; i < 4; i++) {
        int r = bm + (ty << 2) + i;
        if (r < NN) {
            float4 v = make_float4(creg[i][0], creg[i][1], creg[i][2], creg[i][3]);
            *(float4*)&g_h1[(size_t)r * HO + bn + (tx << 2)] = v;
        }
    }
}

// ---------------- per-node attention scores: es1/ed1 (warp per node) ----------------
__global__ __launch_bounds__(256) void scores1_kernel(const float* __restrict__ a_src,
                                                      const float* __restrict__ a_dst) {
    int w = (blockIdx.x * 256 + threadIdx.x) >> 5;
    int lane = threadIdx.x & 31;
    if (w >= NN) return;

    float ss[NH], dd[NH];
#pragma unroll
    for (int h = 0; h < NH; h++) {
        float v = g_h1[(size_t)w * HO + h * 32 + lane];
        ss[h] = v * a_src[h * 32 + lane];
        dd[h] = v * a_dst[h * 32 + lane];
    }
#pragma unroll
    for (int o = 16; o > 0; o >>= 1) {
#pragma unroll
        for (int h = 0; h < NH; h++) {
            ss[h] += __shfl_xor_sync(0xffffffffu, ss[h], o);
            dd[h] += __shfl_xor_sync(0xffffffffu, dd[h], o);
        }
    }
    if (lane == 0) {
#pragma unroll
        for (int h = 0; h < NH; h++) {
            g_es1[w * NH + h] = ss[h];
            g_ed1[w * NH + h] = dd[h];
        }
    }
}

// ---------------- CSR build ----------------
__global__ void zero_kernel() {
    int i = blockIdx.x * blockDim.x + threadIdx.x;
    if (i < NN) { g_deg[i] = 0; g_cursor[i] = 0; }
}

__global__ void hist_kernel(const int* __restrict__ dst) {
    int i = blockIdx.x * blockDim.x + threadIdx.x;
    if (i < EE) atomicAdd(&g_deg[dst[i]], 1);
}

__global__ __launch_bounds__(1024) void scan_kernel() {
    __shared__ int wsum[32];
    __shared__ int carry_s;
    int tid = threadIdx.x, lane = tid & 31, wid = tid >> 5;
    if (tid == 0) { carry_s = 0; g_rowptr[0] = 0; }
    __syncthreads();
    for (int base = 0; base < NN; base += 1024) {
        int i = base + tid;
        int v = (i < NN) ? g_deg[i] : 0;
        int x = v;
#pragma unroll
        for (int o = 1; o < 32; o <<= 1) {
            int y = __shfl_up_sync(0xffffffffu, x, o);
            if (lane >= o) x += y;
        }
        if (lane == 31) wsum[wid] = x;
        __syncthreads();
        if (wid == 0) {
            int s = wsum[lane];
#pragma unroll
            for (int o = 1; o < 32; o <<= 1) {
                int y = __shfl_up_sync(0xffffffffu, s, o);
                if (lane >= o) s += y;
            }
            wsum[lane] = s;
        }
        __syncthreads();
        int incl = x + (wid ? wsum[wid - 1] : 0) + carry_s;
        if (i < NN) g_rowptr[i + 1] = incl;
        __syncthreads();
        if (tid == 1023) carry_s = incl;
        __syncthreads();
    }
}

__global__ void scatter_kernel(const int* __restrict__ src, const int* __restrict__ dst) {
    int i = blockIdx.x * blockDim.x + threadIdx.x;
    if (i < EE) {
        int d = dst[i];
        int pos = atomicAdd(&g_cursor[d], 1);
        g_csrsrc[g_rowptr[d] + pos] = src[i];
    }
}

// ---------------- layer-1 aggregation (warp per dst node), fused softmax + ELU ----------------
__global__ __launch_bounds__(256) void agg1_kernel() {
    int w = (blockIdx.x * 256 + threadIdx.x) >> 5;
    int lane = threadIdx.x & 31;
    if (w >= NN) return;

    int beg = g_rowptr[w], end = g_rowptr[w + 1];

    float4 e0 = *(const float4*)&g_ed1[w * NH];
    float4 e1 = *(const float4*)&g_ed1[w * NH + 4];
    float edv[NH] = {e0.x, e0.y, e0.z, e0.w, e1.x, e1.y, e1.z, e1.w};

    float m[NH];
#pragma unroll
    for (int h = 0; h < NH; h++) m[h] = -3.4e38f;

    // pass 1: segment max per head
    for (int e = beg; e < end; e++) {
        int s = g_csrsrc[e];
        float4 s0 = *(const float4*)&g_es1[s * NH];
        float4 s1 = *(const float4*)&g_es1[s * NH + 4];
        float sv[NH] = {s0.x, s0.y, s0.z, s0.w, s1.x, s1.y, s1.z, s1.w};
#pragma unroll
        for (int h = 0; h < NH; h++) {
            float l = sv[h] + edv[h];
            l = l > 0.f ? l : 0.2f * l;
            m[h] = fmaxf(m[h], l);
        }
    }

    float ssum[NH], acc[NH];
#pragma unroll
    for (int h = 0; h < NH; h++) { ssum[h] = 0.f; acc[h] = 0.f; }

    // pass 2: exp, sum, weighted feature accumulate
    for (int e = beg; e < end; e++) {
        int s = g_csrsrc[e];
        float4 s0 = *(const float4*)&g_es1[s * NH];
        float4 s1 = *(const float4*)&g_es1[s * NH + 4];
        float sv[NH] = {s0.x, s0.y, s0.z, s0.w, s1.x, s1.y, s1.z, s1.w};
        const float* hp = &g_h1[(size_t)s * HO + lane];
#pragma unroll
        for (int h = 0; h < NH; h++) {
            float l = sv[h] + edv[h];
            l = l > 0.f ? l : 0.2f * l;
            float p = __expf(l - m[h]);
            ssum[h] += p;
            acc[h] = fmaf(p, hp[h * 32], acc[h]);
        }
    }

    float* op = &g_out1[(size_t)w * HO + lane];
#pragma unroll
    for (int h = 0; h < NH; h++) {
        float d = ssum[h] > 0.f ? ssum[h] : 1.f;
        float v = acc[h] / d;
        v = v > 0.f ? v : (__expf(v) - 1.f);   // ELU
        op[h * 32] = v;
    }
}

// ---------------- GEMM2 + layer-2 scores: h2 = out1 @ W2, es2/ed2 ----------------
__global__ __launch_bounds__(256) void gemm2_kernel(const float* __restrict__ W2,
                                                    const float* __restrict__ a2s,
                                                    const float* __restrict__ a2d) {
    __shared__ float W2s[HO * CC];   // 16KB
    __shared__ float Xs[16 * HO];    // 16KB
    int tid = threadIdx.x;
    for (int i = tid; i < HO * CC; i += 256) W2s[i] = W2[i];
    const float4* Xg = (const float4*)(g_out1 + (size_t)blockIdx.x * 16 * HO);
    float4* X4 = (float4*)Xs;
    for (int i = tid; i < 16 * HO / 4; i += 256) X4[i] = Xg[i];
    __syncthreads();

    int ln = tid >> 4, c = tid & 15;
    float acc = 0.f;
#pragma unroll 16
    for (int k = 0; k < HO; k++)
        acc = fmaf(Xs[ln * HO + k], W2s[k * CC + c], acc);

    int n = blockIdx.x * 16 + ln;   // 50000 = 3125*16, always valid
    g_h2[n * CC + c] = acc;

    float sv = acc * a2s[c];
    float dv = acc * a2d[c];
#pragma unroll
    for (int o = 8; o > 0; o >>= 1) {
        sv += __shfl_xor_sync(0xffffffffu, sv, o);
        dv += __shfl_xor_sync(0xffffffffu, dv, o);
    }
    if (c == 0) { g_es2[n] = sv; g_ed2[n] = dv; }
}

// ---------------- layer-2 aggregation + log_softmax (warp per dst node) ----------------
__global__ __launch_bounds__(256) void agg2_kernel(float* __restrict__ outp) {
    int w = (blockIdx.x * 256 + threadIdx.x) >> 5;
    int lane = threadIdx.x & 31;
    if (w >= NN) return;

    int beg = g_rowptr[w], end = g_rowptr[w + 1];
    float edv = g_ed2[w];

    float m = -3.4e38f;
    for (int e = beg; e < end; e++) {
        int s = g_csrsrc[e];
        float l = g_es2[s] + edv;
        l = l > 0.f ? l : 0.2f * l;
        m = fmaxf(m, l);
    }

    int c = lane & 15;
    float ssum = 0.f, acc = 0.f;
    for (int e = beg; e < end; e++) {
        int s = g_csrsrc[e];
        float l = g_es2[s] + edv;
        l = l > 0.f ? l : 0.2f * l;
        float p = __expf(l - m);
        ssum += p;
        acc = fmaf(p, g_h2[s * CC + c], acc);
    }
    float d = ssum > 0.f ? ssum : 1.f;
    float v = acc / d;

    // log_softmax over the 16 classes (held one-per-lane, duplicated in upper half-warp)
    float mx = v;
#pragma unroll
    for (int o = 8; o > 0; o >>= 1)
        mx = fmaxf(mx, __shfl_xor_sync(0xffffffffu, mx, o));
    float se = __expf(v - mx);
#pragma unroll
    for (int o = 8; o > 0; o >>= 1)
        se += __shfl_xor_sync(0xffffffffu, se, o);
    float res = v - mx - __logf(se);

    if (lane < 16) outp[(size_t)w * CC + lane] = res;
}

// ---------------- launch ----------------
extern "C" void kernel_launch(void* const* d_in, const int* in_sizes, int n_in,
                              void* d_out, int out_size) {
    const float* x   = (const float*)d_in[0];
    const float* W1  = (const float*)d_in[1];
    const float* a1s = (const float*)d_in[2];
    const float* a1d = (const float*)d_in[3];
    const float* W2  = (const float*)d_in[4];
    const float* a2s = (const float*)d_in[5];
    const float* a2d = (const float*)d_in[6];
    const int*   ei  = (const int*)d_in[7];   // [2, E]: src = ei[0:E], dst = ei[E:2E]
    float* out = (float*)d_out;

    // GEMM1: grid (256/64=4 cols, ceil(50000/64)=782 rows)
    gemm1_kernel<<<dim3(4, 782), 256>>>(x, W1);

    // per-node scores (50000 warps)
    scores1_kernel<<<6250, 256>>>(a1s, a1d);

    // CSR build
    zero_kernel<<<(NN + 255) / 256, 256>>>();
    hist_kernel<<<(EE + 255) / 256, 256>>>(ei + EE);
    scan_kernel<<<1, 1024>>>();
    scatter_kernel<<<(EE + 255) / 256, 256>>>(ei, ei + EE);

    // layer-1 aggregation + ELU
    agg1_kernel<<<6250, 256>>>();

    // GEMM2 + scores
    gemm2_kernel<<<3125, 256>>>(W2, a2s, a2d);

    // layer-2 aggregation + log_softmax
    agg2_kernel<<<6250, 256>>>(out);
}

// round 4
// speedup vs baseline: 1.2720x; 1.2720x over previous
#include <cuda_runtime.h>
#include <cuda_bf16.h>
#include <cstdint>
#include <cstddef>

// Problem constants
#define NN   50000
#define EE   800000
#define KIN  512
#define HO   256    // H*OUT
#define NH   8
#define CC   16

// ---------------- scratch (static device globals; no allocation) ----------------
__device__ __align__(16) float g_h1[(size_t)NN * HO];    // x @ W1
__device__ __align__(16) float g_out1[(size_t)NN * HO];  // layer-1 output (post ELU)
__device__ __align__(16) float g_es1[NN * NH];
__device__ __align__(16) float g_ed1[NN * NH];
__device__ __align__(16) float g_h2[NN * CC];            // out1 @ W2
__device__ float g_es2[NN];
__device__ float g_ed2[NN];
__device__ int   g_deg[NN];
__device__ int   g_rowptr[NN + 1];
__device__ int   g_cursor[NN];
__device__ int   g_csrsrc[EE];

// ================= helpers =================
__device__ __forceinline__ uint32_t smem_u32(const void* p) {
    uint32_t a;
    asm("{ .reg .u64 t; cvta.to.shared.u64 t, %1; cvt.u32.u64 %0, t; }" : "=r"(a) : "l"(p));
    return a;
}

__device__ __forceinline__ uint32_t pkbf(float a, float b, float* ra, float* rb) {
    __nv_bfloat16 ha = __float2bfloat16(a);
    __nv_bfloat16 hb = __float2bfloat16(b);
    *ra = a - __bfloat162float(ha);
    *rb = b - __bfloat162float(hb);
    return (uint32_t)__bfloat16_as_ushort(ha) | ((uint32_t)__bfloat16_as_ushort(hb) << 16);
}
__device__ __forceinline__ uint32_t pkbf2(float a, float b) {
    return (uint32_t)__bfloat16_as_ushort(__float2bfloat16(a)) |
           ((uint32_t)__bfloat16_as_ushort(__float2bfloat16(b)) << 16);
}

__device__ __forceinline__ void ldmA(uint32_t* r, uint32_t addr) {
    asm volatile("ldmatrix.sync.aligned.m8n8.x4.shared.b16 {%0,%1,%2,%3}, [%4];"
                 : "=r"(r[0]), "=r"(r[1]), "=r"(r[2]), "=r"(r[3]) : "r"(addr));
}
__device__ __forceinline__ void ldmBT(uint32_t* r, uint32_t addr) {
    asm volatile("ldmatrix.sync.aligned.m8n8.x2.trans.shared.b16 {%0,%1}, [%2];"
                 : "=r"(r[0]), "=r"(r[1]) : "r"(addr));
}
__device__ __forceinline__ void mma_bf16(float* c, const uint32_t* a, const uint32_t* b) {
    asm volatile("mma.sync.aligned.m16n8k16.row.col.f32.bf16.bf16.f32 "
                 "{%0,%1,%2,%3}, {%4,%5,%6,%7}, {%8,%9}, {%0,%1,%2,%3};"
                 : "+f"(c[0]), "+f"(c[1]), "+f"(c[2]), "+f"(c[3])
                 : "r"(a[0]), "r"(a[1]), "r"(a[2]), "r"(a[3]), "r"(b[0]), "r"(b[1]));
}

// ---------------- GEMM1 via mma.sync bf16 split (hi/lo 3-MMA): h1 = x @ W1 ----------------
// CTA tile 128(M) x 128(N), BK=32, 8 warps in 4(M) x 2(N), warp tile 32x64.
#define BK   32
#define ASTR 40     // padded A row stride (elements) -> 80B, conflict-free ldmatrix
#define BSTR 136    // padded B row stride (elements) -> 272B, conflict-free ldmatrix

__global__ __launch_bounds__(256, 2) void gemm1_mma_kernel(const float* __restrict__ x,
                                                           const float* __restrict__ W1) {
    __shared__ __align__(16) uint16_t Ah[128 * ASTR];
    __shared__ __align__(16) uint16_t Al[128 * ASTR];
    __shared__ __align__(16) uint16_t Bh[BK * BSTR];
    __shared__ __align__(16) uint16_t Bl[BK * BSTR];

    int tid = threadIdx.x, lane = tid & 31, wid = tid >> 5;
    int bm = blockIdx.y * 128, bn = blockIdx.x * 128;
    int wm = (wid >> 1) * 32;   // warp M offset (4 warps)
    int wn = (wid & 1) * 64;    // warp N offset (2 warps)

    float acc[2][8][4];
#pragma unroll
    for (int i = 0; i < 2; i++)
#pragma unroll
        for (int j = 0; j < 8; j++)
#pragma unroll
            for (int q = 0; q < 4; q++) acc[i][j][q] = 0.f;

    // staging indices
    int ar = tid >> 1, akq = (tid & 1) << 4;        // row 0..127, k-quarter 0/16
    bool arv = (bm + ar) < NN;
    const float* aptr = x + (size_t)(bm + ar) * KIN + akq;
    int bk = tid >> 3, bnq = (tid & 7) << 4;        // k-row 0..31, n offset 0..112
    const float* bptr = W1 + (size_t)bk * HO + bn + bnq;

    uint32_t aBaseH = smem_u32(Ah), aBaseL = smem_u32(Al);
    uint32_t bBaseH = smem_u32(Bh), bBaseL = smem_u32(Bl);

    // ldmatrix per-lane address components
    int aRow = (lane & 15);                 // row within 16-row frag
    int aColB = (lane >> 4) << 4;           // +0 or +16 bytes (k halves)
    int bK = (lane & 15);                   // k-row within 16

    for (int c0 = 0; c0 < KIN; c0 += BK) {
        // ---- stage A [128 x 32] hi/lo ----
#pragma unroll
        for (int j = 0; j < 4; j++) {
            float4 v = arv ? *(const float4*)(aptr + c0 + 4 * j)
                           : make_float4(0.f, 0.f, 0.f, 0.f);
            float lx, ly, lz, lw;
            uint32_t h01 = pkbf(v.x, v.y, &lx, &ly);
            uint32_t h23 = pkbf(v.z, v.w, &lz, &lw);
            int idx = ar * ASTR + akq + 4 * j;
            *(uint32_t*)&Ah[idx]     = h01;
            *(uint32_t*)&Ah[idx + 2] = h23;
            *(uint32_t*)&Al[idx]     = pkbf2(lx, ly);
            *(uint32_t*)&Al[idx + 2] = pkbf2(lz, lw);
        }
        // ---- stage B [32 x 128] hi/lo (same [k][n] layout as W1) ----
#pragma unroll
        for (int j = 0; j < 4; j++) {
            float4 v = *(const float4*)(bptr + (size_t)c0 * HO + 4 * j);
            float lx, ly, lz, lw;
            uint32_t h01 = pkbf(v.x, v.y, &lx, &ly);
            uint32_t h23 = pkbf(v.z, v.w, &lz, &lw);
            int idx = bk * BSTR + bnq + 4 * j;
            *(uint32_t*)&Bh[idx]     = h01;
            *(uint32_t*)&Bh[idx + 2] = h23;
            *(uint32_t*)&Bl[idx]     = pkbf2(lx, ly);
            *(uint32_t*)&Bl[idx + 2] = pkbf2(lz, lw);
        }
        __syncthreads();

        // ---- compute: 2 k-steps of 16 ----
#pragma unroll
        for (int kk = 0; kk < BK; kk += 16) {
            uint32_t afh[2][4], afl[2][4];
#pragma unroll
            for (int mf = 0; mf < 2; mf++) {
                uint32_t aoff = (uint32_t)((wm + mf * 16 + aRow) * ASTR + kk) * 2 + aColB;
                ldmA(afh[mf], aBaseH + aoff);
                ldmA(afl[mf], aBaseL + aoff);
            }
#pragma unroll
            for (int nf = 0; nf < 8; nf++) {
                uint32_t bfh[2], bfl[2];
                uint32_t boff = (uint32_t)((kk + bK) * BSTR + wn + nf * 8) * 2;
                ldmBT(bfh, bBaseH + boff);
                ldmBT(bfl, bBaseL + boff);
#pragma unroll
                for (int mf = 0; mf < 2; mf++) {
                    mma_bf16(acc[mf][nf], afh[mf], bfh);
                    mma_bf16(acc[mf][nf], afl[mf], bfh);
                    mma_bf16(acc[mf][nf], afh[mf], bfl);
                }
            }
        }
        __syncthreads();
    }

    // ---- epilogue: write fragments to g_h1 ----
    int rBase = bm + wm + (lane >> 2);
    int cBase = bn + wn + (lane & 3) * 2;
#pragma unroll
    for (int mf = 0; mf < 2; mf++) {
#pragma unroll
        for (int nf = 0; nf < 8; nf++) {
            int r0 = rBase + mf * 16;
            int col = cBase + nf * 8;
            if (r0 < NN)
                *(float2*)&g_h1[(size_t)r0 * HO + col] = make_float2(acc[mf][nf][0], acc[mf][nf][1]);
            if (r0 + 8 < NN)
                *(float2*)&g_h1[(size_t)(r0 + 8) * HO + col] = make_float2(acc[mf][nf][2], acc[mf][nf][3]);
        }
    }
}

// ---------------- per-node attention scores: es1/ed1 (warp per node) ----------------
__global__ __launch_bounds__(256) void scores1_kernel(const float* __restrict__ a_src,
                                                      const float* __restrict__ a_dst) {
    int w = (blockIdx.x * 256 + threadIdx.x) >> 5;
    int lane = threadIdx.x & 31;
    if (w >= NN) return;

    float ss[NH], dd[NH];
#pragma unroll
    for (int h = 0; h < NH; h++) {
        float v = g_h1[(size_t)w * HO + h * 32 + lane];
        ss[h] = v * a_src[h * 32 + lane];
        dd[h] = v * a_dst[h * 32 + lane];
    }
#pragma unroll
    for (int o = 16; o > 0; o >>= 1) {
#pragma unroll
        for (int h = 0; h < NH; h++) {
            ss[h] += __shfl_xor_sync(0xffffffffu, ss[h], o);
            dd[h] += __shfl_xor_sync(0xffffffffu, dd[h], o);
        }
    }
    if (lane == 0) {
#pragma unroll
        for (int h = 0; h < NH; h++) {
            g_es1[w * NH + h] = ss[h];
            g_ed1[w * NH + h] = dd[h];
        }
    }
}

// ---------------- CSR build ----------------
__global__ void zero_kernel() {
    int i = blockIdx.x * blockDim.x + threadIdx.x;
    if (i < NN) { g_deg[i] = 0; g_cursor[i] = 0; }
}

__global__ void hist_kernel(const int* __restrict__ dst) {
    int i = blockIdx.x * blockDim.x + threadIdx.x;
    if (i < EE) atomicAdd(&g_deg[dst[i]], 1);
}

__global__ __launch_bounds__(1024) void scan_kernel() {
    __shared__ int wsum[32];
    __shared__ int carry_s;
    int tid = threadIdx.x, lane = tid & 31, wid = tid >> 5;
    if (tid == 0) { carry_s = 0; g_rowptr[0] = 0; }
    __syncthreads();
    for (int base = 0; base < NN; base += 1024) {
        int i = base + tid;
        int v = (i < NN) ? g_deg[i] : 0;
        int x = v;
#pragma unroll
        for (int o = 1; o < 32; o <<= 1) {
            int y = __shfl_up_sync(0xffffffffu, x, o);
            if (lane >= o) x += y;
        }
        if (lane == 31) wsum[wid] = x;
        __syncthreads();
        if (wid == 0) {
            int s = wsum[lane];
#pragma unroll
            for (int o = 1; o < 32; o <<= 1) {
                int y = __shfl_up_sync(0xffffffffu, s, o);
                if (lane >= o) s += y;
            }
            wsum[lane] = s;
        }
        __syncthreads();
        int incl = x + (wid ? wsum[wid - 1] : 0) + carry_s;
        if (i < NN) g_rowptr[i + 1] = incl;
        __syncthreads();
        if (tid == 1023) carry_s = incl;
        __syncthreads();
    }
}

__global__ void scatter_kernel(const int* __restrict__ src, const int* __restrict__ dst) {
    int i = blockIdx.x * blockDim.x + threadIdx.x;
    if (i < EE) {
        int d = dst[i];
        int pos = atomicAdd(&g_cursor[d], 1);
        g_csrsrc[g_rowptr[d] + pos] = src[i];
    }
}

// ---------------- layer-1 aggregation (warp per dst node), fused softmax + ELU ----------------
__global__ __launch_bounds__(256) void agg1_kernel() {
    int w = (blockIdx.x * 256 + threadIdx.x) >> 5;
    int lane = threadIdx.x & 31;
    if (w >= NN) return;

    int beg = g_rowptr[w], end = g_rowptr[w + 1];

    float4 e0 = *(const float4*)&g_ed1[w * NH];
    float4 e1 = *(const float4*)&g_ed1[w * NH + 4];
    float edv[NH] = {e0.x, e0.y, e0.z, e0.w, e1.x, e1.y, e1.z, e1.w};

    float m[NH];
#pragma unroll
    for (int h = 0; h < NH; h++) m[h] = -3.4e38f;

    for (int e = beg; e < end; e++) {
        int s = g_csrsrc[e];
        float4 s0 = *(const float4*)&g_es1[s * NH];
        float4 s1 = *(const float4*)&g_es1[s * NH + 4];
        float sv[NH] = {s0.x, s0.y, s0.z, s0.w, s1.x, s1.y, s1.z, s1.w};
#pragma unroll
        for (int h = 0; h < NH; h++) {
            float l = sv[h] + edv[h];
            l = l > 0.f ? l : 0.2f * l;
            m[h] = fmaxf(m[h], l);
        }
    }

    float ssum[NH], acc[NH];
#pragma unroll
    for (int h = 0; h < NH; h++) { ssum[h] = 0.f; acc[h] = 0.f; }

    for (int e = beg; e < end; e++) {
        int s = g_csrsrc[e];
        float4 s0 = *(const float4*)&g_es1[s * NH];
        float4 s1 = *(const float4*)&g_es1[s * NH + 4];
        float sv[NH] = {s0.x, s0.y, s0.z, s0.w, s1.x, s1.y, s1.z, s1.w};
        const float* hp = &g_h1[(size_t)s * HO + lane];
#pragma unroll
        for (int h = 0; h < NH; h++) {
            float l = sv[h] + edv[h];
            l = l > 0.f ? l : 0.2f * l;
            float p = __expf(l - m[h]);
            ssum[h] += p;
            acc[h] = fmaf(p, hp[h * 32], acc[h]);
        }
    }

    float* op = &g_out1[(size_t)w * HO + lane];
#pragma unroll
    for (int h = 0; h < NH; h++) {
        float d = ssum[h] > 0.f ? ssum[h] : 1.f;
        float v = acc[h] / d;
        v = v > 0.f ? v : (__expf(v) - 1.f);   // ELU
        op[h * 32] = v;
    }
}

// ---------------- GEMM2 + layer-2 scores ----------------
__global__ __launch_bounds__(256) void gemm2_kernel(const float* __restrict__ W2,
                                                    const float* __restrict__ a2s,
                                                    const float* __restrict__ a2d) {
    __shared__ float W2s[HO * CC];   // 16KB
    __shared__ float Xs[16 * HO];    // 16KB
    int tid = threadIdx.x;
    for (int i = tid; i < HO * CC; i += 256) W2s[i] = W2[i];
    const float4* Xg = (const float4*)(g_out1 + (size_t)blockIdx.x * 16 * HO);
    float4* X4 = (float4*)Xs;
    for (int i = tid; i < 16 * HO / 4; i += 256) X4[i] = Xg[i];
    __syncthreads();

    int ln = tid >> 4, c = tid & 15;
    float acc = 0.f;
#pragma unroll 16
    for (int k = 0; k < HO; k++)
        acc = fmaf(Xs[ln * HO + k], W2s[k * CC + c], acc);

    int n = blockIdx.x * 16 + ln;
    g_h2[n * CC + c] = acc;

    float sv = acc * a2s[c];
    float dv = acc * a2d[c];
#pragma unroll
    for (int o = 8; o > 0; o >>= 1) {
        sv += __shfl_xor_sync(0xffffffffu, sv, o);
        dv += __shfl_xor_sync(0xffffffffu, dv, o);
    }
    if (c == 0) { g_es2[n] = sv; g_ed2[n] = dv; }
}

// ---------------- layer-2 aggregation + log_softmax (warp per dst node) ----------------
__global__ __launch_bounds__(256) void agg2_kernel(float* __restrict__ outp) {
    int w = (blockIdx.x * 256 + threadIdx.x) >> 5;
    int lane = threadIdx.x & 31;
    if (w >= NN) return;

    int beg = g_rowptr[w], end = g_rowptr[w + 1];
    float edv = g_ed2[w];

    float m = -3.4e38f;
    for (int e = beg; e < end; e++) {
        int s = g_csrsrc[e];
        float l = g_es2[s] + edv;
        l = l > 0.f ? l : 0.2f * l;
        m = fmaxf(m, l);
    }

    int c = lane & 15;
    float ssum = 0.f, acc = 0.f;
    for (int e = beg; e < end; e++) {
        int s = g_csrsrc[e];
        float l = g_es2[s] + edv;
        l = l > 0.f ? l : 0.2f * l;
        float p = __expf(l - m);
        ssum += p;
        acc = fmaf(p, g_h2[s * CC + c], acc);
    }
    float d = ssum > 0.f ? ssum : 1.f;
    float v = acc / d;

    float mx = v;
#pragma unroll
    for (int o = 8; o > 0; o >>= 1)
        mx = fmaxf(mx, __shfl_xor_sync(0xffffffffu, mx, o));
    float se = __expf(v - mx);
#pragma unroll
    for (int o = 8; o > 0; o >>= 1)
        se += __shfl_xor_sync(0xffffffffu, se, o);
    float res = v - mx - __logf(se);

    if (lane < 16) outp[(size_t)w * CC + lane] = res;
}

// ---------------- launch ----------------
extern "C" void kernel_launch(void* const* d_in, const int* in_sizes, int n_in,
                              void* d_out, int out_size) {
    const float* x   = (const float*)d_in[0];
    const float* W1  = (const float*)d_in[1];
    const float* a1s = (const float*)d_in[2];
    const float* a1d = (const float*)d_in[3];
    const float* W2  = (const float*)d_in[4];
    const float* a2s = (const float*)d_in[5];
    const float* a2d = (const float*)d_in[6];
    const int*   ei  = (const int*)d_in[7];   // [2, E]: src = ei[0:E], dst = ei[E:2E]
    float* out = (float*)d_out;

    // GEMM1 on tensor cores (mma.sync bf16 split): grid (2 n-tiles, 391 m-tiles)
    gemm1_mma_kernel<<<dim3(2, 391), 256>>>(x, W1);

    // per-node scores (50000 warps)
    scores1_kernel<<<6250, 256>>>(a1s, a1d);

    // CSR build
    zero_kernel<<<(NN + 255) / 256, 256>>>();
    hist_kernel<<<(EE + 255) / 256, 256>>>(ei + EE);
    scan_kernel<<<1, 1024>>>();
    scatter_kernel<<<(EE + 255) / 256, 256>>>(ei, ei + EE);

    // layer-1 aggregation + ELU
    agg1_kernel<<<6250, 256>>>();

    // GEMM2 + scores
    gemm2_kernel<<<3125, 256>>>(W2, a2s, a2d);

    // layer-2 aggregation + log_softmax
    agg2_kernel<<<6250, 256>>>(out);
}

// round 5
// speedup vs baseline: 1.6838x; 1.3238x over previous
#include <cuda_runtime.h>
#include <cuda_bf16.h>
#include <cstdint>
#include <cstddef>

// Problem constants
#define NN   50000
#define EE   800000
#define KIN  512
#define HO   256    // H*OUT
#define NH   8
#define CC   16

// ---------------- scratch (static device globals; no allocation) ----------------
__device__ __align__(16) float g_h1[(size_t)NN * HO];    // x @ W1
__device__ __align__(16) float g_out1[(size_t)NN * HO];  // layer-1 output (post ELU)
__device__ __align__(16) float g_es1[NN * NH];
__device__ __align__(16) float g_ed1[NN * NH];
__device__ __align__(16) float g_h2[NN * CC];            // out1 @ W2
__device__ float g_es2[NN];
__device__ float g_ed2[NN];
__device__ int   g_deg[NN];
__device__ int   g_rowptr[NN + 1];
__device__ int   g_cursor[NN];
__device__ int   g_csrsrc[EE];
__device__ int   g_bsum[64];
// bf16 split copies of x and W1
__device__ __align__(16) unsigned short g_xh[(size_t)NN * KIN];
__device__ __align__(16) unsigned short g_xl[(size_t)NN * KIN];
__device__ __align__(16) unsigned short g_w1h[KIN * HO];
__device__ __align__(16) unsigned short g_w1l[KIN * HO];

// ================= helpers =================
__device__ __forceinline__ uint32_t smem_u32(const void* p) {
    uint32_t a;
    asm("{ .reg .u64 t; cvta.to.shared.u64 t, %1; cvt.u32.u64 %0, t; }" : "=r"(a) : "l"(p));
    return a;
}
__device__ __forceinline__ uint32_t pkbf(float a, float b, float* ra, float* rb) {
    __nv_bfloat16 ha = __float2bfloat16(a);
    __nv_bfloat16 hb = __float2bfloat16(b);
    *ra = a - __bfloat162float(ha);
    *rb = b - __bfloat162float(hb);
    return (uint32_t)__bfloat16_as_ushort(ha) | ((uint32_t)__bfloat16_as_ushort(hb) << 16);
}
__device__ __forceinline__ uint32_t pkbf2(float a, float b) {
    return (uint32_t)__bfloat16_as_ushort(__float2bfloat16(a)) |
           ((uint32_t)__bfloat16_as_ushort(__float2bfloat16(b)) << 16);
}
__device__ __forceinline__ void ldmA(uint32_t* r, uint32_t addr) {
    asm volatile("ldmatrix.sync.aligned.m8n8.x4.shared.b16 {%0,%1,%2,%3}, [%4];"
                 : "=r"(r[0]), "=r"(r[1]), "=r"(r[2]), "=r"(r[3]) : "r"(addr));
}
__device__ __forceinline__ void ldmBT(uint32_t* r, uint32_t addr) {
    asm volatile("ldmatrix.sync.aligned.m8n8.x2.trans.shared.b16 {%0,%1}, [%2];"
                 : "=r"(r[0]), "=r"(r[1]) : "r"(addr));
}
__device__ __forceinline__ void mma_bf16(float* c, const uint32_t* a, const uint32_t* b) {
    asm volatile("mma.sync.aligned.m16n8k16.row.col.f32.bf16.bf16.f32 "
                 "{%0,%1,%2,%3}, {%4,%5,%6,%7}, {%8,%9}, {%0,%1,%2,%3};"
                 : "+f"(c[0]), "+f"(c[1]), "+f"(c[2]), "+f"(c[3])
                 : "r"(a[0]), "r"(a[1]), "r"(a[2]), "r"(a[3]), "r"(b[0]), "r"(b[1]));
}
#define CP16(dst, src) \
    asm volatile("cp.async.ca.shared.global [%0], [%1], 16;" :: "r"(dst), "l"(src))
#define CP_COMMIT() asm volatile("cp.async.commit_group;")
#define CP_WAIT(n)  asm volatile("cp.async.wait_group %0;" :: "n"(n))

// ---------------- one-shot fp32 -> bf16 hi/lo conversion ----------------
__global__ __launch_bounds__(256) void convert_kernel(const float* __restrict__ x,
                                                      const float* __restrict__ W1) {
    const size_t NX4 = (size_t)NN * KIN / 4;   // 6,400,000
    const size_t NW4 = (size_t)KIN * HO / 4;   // 32,768
    size_t i = (size_t)blockIdx.x * 256 + threadIdx.x;
    if (i < NX4) {
        float4 v = ((const float4*)x)[i];
        float lx, ly, lz, lw;
        uint2 hi = make_uint2(pkbf(v.x, v.y, &lx, &ly), pkbf(v.z, v.w, &lz, &lw));
        uint2 lo = make_uint2(pkbf2(lx, ly), pkbf2(lz, lw));
        ((uint2*)g_xh)[i] = hi;
        ((uint2*)g_xl)[i] = lo;
    } else if (i < NX4 + NW4) {
        size_t j = i - NX4;
        float4 v = ((const float4*)W1)[j];
        float lx, ly, lz, lw;
        uint2 hi = make_uint2(pkbf(v.x, v.y, &lx, &ly), pkbf(v.z, v.w, &lz, &lw));
        uint2 lo = make_uint2(pkbf2(lx, ly), pkbf2(lz, lw));
        ((uint2*)g_w1h)[j] = hi;
        ((uint2*)g_w1l)[j] = lo;
    }
}

// ---------------- GEMM1 via mma.sync bf16 split (3-MMA), cp.async double-buffered ----------------
// CTA tile 128(M) x 128(N), BK=32, 8 warps 4(M)x2(N), warp tile 32x64.
#define BK    32
#define ASTR  40     // A row stride elems (80B, mult of 16, ldmatrix conflict-free)
#define BSTR  136    // B row stride elems (272B, mult of 16, conflict-free)
#define A_BYTES (128 * ASTR * 2)   // 10240
#define B_BYTES (BK * BSTR * 2)    // 8704
#define STG_BYTES (2 * A_BYTES + 2 * B_BYTES)  // 37888 per stage
#define OFF_AH 0
#define OFF_AL A_BYTES
#define OFF_BH (2 * A_BYTES)
#define OFF_BL (2 * A_BYTES + B_BYTES)
#define GEMM1_SMEM (2 * STG_BYTES)             // 75776

__global__ __launch_bounds__(256, 2) void gemm1_mma_kernel() {
    extern __shared__ __align__(16) char sm[];
    uint32_t sbase = smem_u32(sm);

    int tid = threadIdx.x, lane = tid & 31, wid = tid >> 5;
    int bm = blockIdx.y * 128, bn = blockIdx.x * 128;
    int wm = (wid >> 1) * 32, wn = (wid & 1) * 64;

    float acc[2][8][4];
#pragma unroll
    for (int i = 0; i < 2; i++)
#pragma unroll
        for (int j = 0; j < 8; j++)
#pragma unroll
            for (int q = 0; q < 4; q++) acc[i][j][q] = 0.f;

    // A chunk mapping: 512 chunks of 16B (128 rows x 4); this thread does chunks tid, tid+256
    int ar0 = tid >> 2, aj0 = tid & 3;
    int ar1 = (tid + 256) >> 2, aj1 = aj0;
    int gr0 = bm + ar0; if (gr0 >= NN) gr0 = NN - 1;   // clamp: garbage only affects invalid rows
    int gr1 = bm + ar1; if (gr1 >= NN) gr1 = NN - 1;
    const unsigned short* axh0 = g_xh + (size_t)gr0 * KIN + aj0 * 8;
    const unsigned short* axh1 = g_xh + (size_t)gr1 * KIN + aj1 * 8;
    const unsigned short* axl0 = g_xl + (size_t)gr0 * KIN + aj0 * 8;
    const unsigned short* axl1 = g_xl + (size_t)gr1 * KIN + aj1 * 8;
    uint32_t adst0 = ar0 * (ASTR * 2) + aj0 * 16;
    uint32_t adst1 = ar1 * (ASTR * 2) + aj1 * 16;

    // B chunk mapping: 512 chunks (32 k-rows x 16 chunks of 8 cols)
    int bk0 = tid >> 4, bj0 = tid & 15;
    int bk1 = (tid + 256) >> 4, bj1 = bj0;
    const unsigned short* bwh0 = g_w1h + (size_t)bk0 * HO + bn + bj0 * 8;
    const unsigned short* bwh1 = g_w1h + (size_t)bk1 * HO + bn + bj1 * 8;
    const unsigned short* bwl0 = g_w1l + (size_t)bk0 * HO + bn + bj0 * 8;
    const unsigned short* bwl1 = g_w1l + (size_t)bk1 * HO + bn + bj1 * 8;
    uint32_t bdst0 = bk0 * (BSTR * 2) + bj0 * 16;
    uint32_t bdst1 = bk1 * (BSTR * 2) + bj1 * 16;

    auto load_stage = [&](int s, int c0) {
        uint32_t sb = sbase + s * STG_BYTES;
        CP16(sb + OFF_AH + adst0, axh0 + c0);
        CP16(sb + OFF_AH + adst1, axh1 + c0);
        CP16(sb + OFF_AL + adst0, axl0 + c0);
        CP16(sb + OFF_AL + adst1, axl1 + c0);
        CP16(sb + OFF_BH + bdst0, bwh0 + (size_t)c0 * HO);
        CP16(sb + OFF_BH + bdst1, bwh1 + (size_t)c0 * HO);
        CP16(sb + OFF_BL + bdst0, bwl0 + (size_t)c0 * HO);
        CP16(sb + OFF_BL + bdst1, bwl1 + (size_t)c0 * HO);
    };

    int aRow = (lane & 15);
    int aColB = (lane >> 4) << 4;
    int bK = (lane & 15);

    load_stage(0, 0);
    CP_COMMIT();

    for (int it = 0; it < KIN / BK; it++) {
        if (it + 1 < KIN / BK) {
            load_stage((it + 1) & 1, (it + 1) * BK);
            CP_COMMIT();
            CP_WAIT(1);
        } else {
            CP_WAIT(0);
        }
        __syncthreads();

        uint32_t sb = sbase + (it & 1) * STG_BYTES;
        uint32_t aH = sb + OFF_AH, aL = sb + OFF_AL;
        uint32_t bH = sb + OFF_BH, bL = sb + OFF_BL;

#pragma unroll
        for (int kk = 0; kk < BK; kk += 16) {
            uint32_t afh[2][4], afl[2][4];
#pragma unroll
            for (int mf = 0; mf < 2; mf++) {
                uint32_t aoff = (uint32_t)((wm + mf * 16 + aRow) * ASTR + kk) * 2 + aColB;
                ldmA(afh[mf], aH + aoff);
                ldmA(afl[mf], aL + aoff);
            }
#pragma unroll
            for (int nf = 0; nf < 8; nf++) {
                uint32_t bfh[2], bfl[2];
                uint32_t boff = (uint32_t)((kk + bK) * BSTR + wn + nf * 8) * 2;
                ldmBT(bfh, bH + boff);
                ldmBT(bfl, bL + boff);
#pragma unroll
                for (int mf = 0; mf < 2; mf++) {
                    mma_bf16(acc[mf][nf], afh[mf], bfh);
                    mma_bf16(acc[mf][nf], afl[mf], bfh);
                    mma_bf16(acc[mf][nf], afh[mf], bfl);
                }
            }
        }
        __syncthreads();
    }

    // epilogue
    int rBase = bm + wm + (lane >> 2);
    int cBase = bn + wn + (lane & 3) * 2;
#pragma unroll
    for (int mf = 0; mf < 2; mf++) {
#pragma unroll
        for (int nf = 0; nf < 8; nf++) {
            int r0 = rBase + mf * 16;
            int col = cBase + nf * 8;
            if (r0 < NN)
                *(float2*)&g_h1[(size_t)r0 * HO + col] = make_float2(acc[mf][nf][0], acc[mf][nf][1]);
            if (r0 + 8 < NN)
                *(float2*)&g_h1[(size_t)(r0 + 8) * HO + col] = make_float2(acc[mf][nf][2], acc[mf][nf][3]);
        }
    }
}

// ---------------- per-node attention scores ----------------
__global__ __launch_bounds__(256) void scores1_kernel(const float* __restrict__ a_src,
                                                      const float* __restrict__ a_dst) {
    int w = (blockIdx.x * 256 + threadIdx.x) >> 5;
    int lane = threadIdx.x & 31;
    if (w >= NN) return;

    float ss[NH], dd[NH];
#pragma unroll
    for (int h = 0; h < NH; h++) {
        float v = g_h1[(size_t)w * HO + h * 32 + lane];
        ss[h] = v * a_src[h * 32 + lane];
        dd[h] = v * a_dst[h * 32 + lane];
    }
#pragma unroll
    for (int o = 16; o > 0; o >>= 1) {
#pragma unroll
        for (int h = 0; h < NH; h++) {
            ss[h] += __shfl_xor_sync(0xffffffffu, ss[h], o);
            dd[h] += __shfl_xor_sync(0xffffffffu, dd[h], o);
        }
    }
    if (lane == 0) {
#pragma unroll
        for (int h = 0; h < NH; h++) {
            g_es1[w * NH + h] = ss[h];
            g_ed1[w * NH + h] = dd[h];
        }
    }
}

// ---------------- CSR build ----------------
__global__ void zero_kernel() {
    int i = blockIdx.x * blockDim.x + threadIdx.x;
    if (i < NN) { g_deg[i] = 0; g_cursor[i] = 0; }
}

__global__ void hist_kernel(const int* __restrict__ dst) {
    int i = blockIdx.x * blockDim.x + threadIdx.x;
    if (i < EE) atomicAdd(&g_deg[dst[i]], 1);
}

// 3-stage parallel scan: 49 blocks x 1024
__global__ __launch_bounds__(1024) void scan1_kernel() {
    __shared__ int wsum[32];
    int tid = threadIdx.x, lane = tid & 31, wid = tid >> 5;
    int i = blockIdx.x * 1024 + tid;
    int v = (i < NN) ? g_deg[i] : 0;
    int x = v;
#pragma unroll
    for (int o = 1; o < 32; o <<= 1) {
        int y = __shfl_up_sync(0xffffffffu, x, o);
        if (lane >= o) x += y;
    }
    if (lane == 31) wsum[wid] = x;
    __syncthreads();
    if (wid == 0) {
        int s = wsum[lane];
#pragma unroll
        for (int o = 1; o < 32; o <<= 1) {
            int y = __shfl_up_sync(0xffffffffu, s, o);
            if (lane >= o) s += y;
        }
        wsum[lane] = s;
    }
    __syncthreads();
    int incl = x + (wid ? wsum[wid - 1] : 0);
    if (i < NN) g_rowptr[i + 1] = incl;
    if (tid == 1023) g_bsum[blockIdx.x] = incl;
}

__global__ void scan2_kernel() {
    __shared__ int wtot;
    int tid = threadIdx.x, lane = tid & 31, wid = tid >> 5;   // 64 threads
    int v = (tid < 49) ? g_bsum[tid] : 0;
    int x = v;
#pragma unroll
    for (int o = 1; o < 32; o <<= 1) {
        int y = __shfl_up_sync(0xffffffffu, x, o);
        if (lane >= o) x += y;
    }
    if (wid == 0 && lane == 31) wtot = x;
    __syncthreads();
    int incl = x + (wid ? wtot : 0);
    if (tid < 49) g_bsum[tid] = incl - v;   // exclusive offset
}

__global__ __launch_bounds__(1024) void scan3_kernel() {
    int tid = threadIdx.x;
    int i = blockIdx.x * 1024 + tid;
    int off = g_bsum[blockIdx.x];
    if (i < NN) g_rowptr[i + 1] += off;
    if (blockIdx.x == 0 && tid == 0) g_rowptr[0] = 0;
}

__global__ void scatter_kernel(const int* __restrict__ src, const int* __restrict__ dst) {
    int i = blockIdx.x * blockDim.x + threadIdx.x;
    if (i < EE) {
        int d = dst[i];
        int pos = atomicAdd(&g_cursor[d], 1);
        g_csrsrc[g_rowptr[d] + pos] = src[i];
    }
}

// ---------------- layer-1 aggregation: single-pass softmax (no max shift) + ELU ----------------
__global__ __launch_bounds__(256) void agg1_kernel() {
    int w = (blockIdx.x * 256 + threadIdx.x) >> 5;
    int lane = threadIdx.x & 31;
    if (w >= NN) return;

    int beg = g_rowptr[w], end = g_rowptr[w + 1];

    float4 e0 = *(const float4*)&g_ed1[w * NH];
    float4 e1 = *(const float4*)&g_ed1[w * NH + 4];
    float edv[NH] = {e0.x, e0.y, e0.z, e0.w, e1.x, e1.y, e1.z, e1.w};

    float ssum[NH], acc[NH];
#pragma unroll
    for (int h = 0; h < NH; h++) { ssum[h] = 0.f; acc[h] = 0.f; }

    for (int e = beg; e < end; e++) {
        int s = g_csrsrc[e];
        float4 s0 = *(const float4*)&g_es1[s * NH];
        float4 s1 = *(const float4*)&g_es1[s * NH + 4];
        float sv[NH] = {s0.x, s0.y, s0.z, s0.w, s1.x, s1.y, s1.z, s1.w};
        const float* hp = &g_h1[(size_t)s * HO + lane];
#pragma unroll
        for (int h = 0; h < NH; h++) {
            float l = sv[h] + edv[h];
            l = l > 0.f ? l : 0.2f * l;
            float p = __expf(l);
            ssum[h] += p;
            acc[h] = fmaf(p, hp[h * 32], acc[h]);
        }
    }

    float* op = &g_out1[(size_t)w * HO + lane];
#pragma unroll
    for (int h = 0; h < NH; h++) {
        float d = ssum[h] > 0.f ? ssum[h] : 1.f;
        float v = acc[h] / d;
        v = v > 0.f ? v : (__expf(v) - 1.f);   // ELU
        op[h * 32] = v;
    }
}

// ---------------- GEMM2 + layer-2 scores ----------------
__global__ __launch_bounds__(256) void gemm2_kernel(const float* __restrict__ W2,
                                                    const float* __restrict__ a2s,
                                                    const float* __restrict__ a2d) {
    __shared__ float W2s[HO * CC];
    __shared__ float Xs[16 * HO];
    int tid = threadIdx.x;
    for (int i = tid; i < HO * CC; i += 256) W2s[i] = W2[i];
    const float4* Xg = (const float4*)(g_out1 + (size_t)blockIdx.x * 16 * HO);
    float4* X4 = (float4*)Xs;
    for (int i = tid; i < 16 * HO / 4; i += 256) X4[i] = Xg[i];
    __syncthreads();

    int ln = tid >> 4, c = tid & 15;
    float acc = 0.f;
#pragma unroll 16
    for (int k = 0; k < HO; k++)
        acc = fmaf(Xs[ln * HO + k], W2s[k * CC + c], acc);

    int n = blockIdx.x * 16 + ln;
    g_h2[n * CC + c] = acc;

    float sv = acc * a2s[c];
    float dv = acc * a2d[c];
#pragma unroll
    for (int o = 8; o > 0; o >>= 1) {
        sv += __shfl_xor_sync(0xffffffffu, sv, o);
        dv += __shfl_xor_sync(0xffffffffu, dv, o);
    }
    if (c == 0) { g_es2[n] = sv; g_ed2[n] = dv; }
}

// ---------------- layer-2 aggregation (single-pass) + log_softmax ----------------
__global__ __launch_bounds__(256) void agg2_kernel(float* __restrict__ outp) {
    int w = (blockIdx.x * 256 + threadIdx.x) >> 5;
    int lane = threadIdx.x & 31;
    if (w >= NN) return;

    int beg = g_rowptr[w], end = g_rowptr[w + 1];
    float edv = g_ed2[w];

    int c = lane & 15;
    float ssum = 0.f, acc = 0.f;
    for (int e = beg; e < end; e++) {
        int s = g_csrsrc[e];
        float l = g_es2[s] + edv;
        l = l > 0.f ? l : 0.2f * l;
        float p = __expf(l);
        ssum += p;
        acc = fmaf(p, g_h2[s * CC + c], acc);
    }
    float d = ssum > 0.f ? ssum : 1.f;
    float v = acc / d;

    float mx = v;
#pragma unroll
    for (int o = 8; o > 0; o >>= 1)
        mx = fmaxf(mx, __shfl_xor_sync(0xffffffffu, mx, o));
    float se = __expf(v - mx);
#pragma unroll
    for (int o = 8; o > 0; o >>= 1)
        se += __shfl_xor_sync(0xffffffffu, se, o);
    float res = v - mx - __logf(se);

    if (lane < 16) outp[(size_t)w * CC + lane] = res;
}

// ---------------- launch ----------------
extern "C" void kernel_launch(void* const* d_in, const int* in_sizes, int n_in,
                              void* d_out, int out_size) {
    const float* x   = (const float*)d_in[0];
    const float* W1  = (const float*)d_in[1];
    const float* a1s = (const float*)d_in[2];
    const float* a1d = (const float*)d_in[3];
    const float* W2  = (const float*)d_in[4];
    const float* a2s = (const float*)d_in[5];
    const float* a2d = (const float*)d_in[6];
    const int*   ei  = (const int*)d_in[7];   // src = ei[0:E], dst = ei[E:2E]
    float* out = (float*)d_out;

    cudaFuncSetAttribute(gemm1_mma_kernel, cudaFuncAttributeMaxDynamicSharedMemorySize, GEMM1_SMEM);

    // fp32 -> bf16 hi/lo (x and W1)
    const size_t NCV = ((size_t)NN * KIN / 4 + (size_t)KIN * HO / 4 + 255) / 256;
    convert_kernel<<<(unsigned)NCV, 256>>>(x, W1);

    // GEMM1 tensor path
    gemm1_mma_kernel<<<dim3(2, 391), 256, GEMM1_SMEM>>>();

    // per-node scores
    scores1_kernel<<<6250, 256>>>(a1s, a1d);

    // CSR build
    zero_kernel<<<(NN + 255) / 256, 256>>>();
    hist_kernel<<<(EE + 255) / 256, 256>>>(ei + EE);
    scan1_kernel<<<49, 1024>>>();
    scan2_kernel<<<1, 64>>>();
    scan3_kernel<<<49, 1024>>>();
    scatter_kernel<<<(EE + 255) / 256, 256>>>(ei, ei + EE);

    // layer-1 aggregation + ELU
    agg1_kernel<<<6250, 256>>>();

    // GEMM2 + scores
    gemm2_kernel<<<3125, 256>>>(W2, a2s, a2d);

    // layer-2 aggregation + log_softmax
    agg2_kernel<<<6250, 256>>>(out);
}

// round 7
// speedup vs baseline: 2.0226x; 1.2012x over previous
#include <cuda_runtime.h>
#include <cuda_bf16.h>
#include <cstdint>
#include <cstddef>

// Problem constants
#define NN   50000
#define EE   800000
#define KIN  512
#define HO   256    // H*OUT
#define NH   8
#define CC   16

// ---------------- scratch (static device globals; no allocation) ----------------
__device__ __align__(16) float g_h1[(size_t)NN * HO];    // x @ W1
__device__ __align__(16) float g_out1[(size_t)NN * HO];  // layer-1 output (post ELU)
__device__ __align__(16) float g_es1[NN * NH];
__device__ __align__(16) float g_ed1[NN * NH];
__device__ __align__(16) float g_h2[NN * CC];            // out1 @ W2
__device__ float g_es2[NN];
__device__ float g_ed2[NN];
__device__ int   g_deg[NN];
__device__ int   g_rowptr[NN + 1];
__device__ int   g_cursor[NN];
__device__ int   g_csrsrc[EE];
__device__ int   g_bsum[64];
// bf16 split copies of x and W1
__device__ __align__(16) unsigned short g_xh[(size_t)NN * KIN];
__device__ __align__(16) unsigned short g_xl[(size_t)NN * KIN];
__device__ __align__(16) unsigned short g_w1h[KIN * HO];
__device__ __align__(16) unsigned short g_w1l[KIN * HO];

// ================= helpers =================
__device__ __forceinline__ uint32_t smem_u32(const void* p) {
    uint32_t a;
    asm("{ .reg .u64 t; cvta.to.shared.u64 t, %1; cvt.u32.u64 %0, t; }" : "=r"(a) : "l"(p));
    return a;
}
__device__ __forceinline__ uint32_t pkbf(float a, float b, float* ra, float* rb) {
    __nv_bfloat16 ha = __float2bfloat16(a);
    __nv_bfloat16 hb = __float2bfloat16(b);
    *ra = a - __bfloat162float(ha);
    *rb = b - __bfloat162float(hb);
    return (uint32_t)__bfloat16_as_ushort(ha) | ((uint32_t)__bfloat16_as_ushort(hb) << 16);
}
__device__ __forceinline__ uint32_t pkbf2(float a, float b) {
    return (uint32_t)__bfloat16_as_ushort(__float2bfloat16(a)) |
           ((uint32_t)__bfloat16_as_ushort(__float2bfloat16(b)) << 16);
}
__device__ __forceinline__ void ldmA(uint32_t* r, uint32_t addr) {
    asm volatile("ldmatrix.sync.aligned.m8n8.x4.shared.b16 {%0,%1,%2,%3}, [%4];"
                 : "=r"(r[0]), "=r"(r[1]), "=r"(r[2]), "=r"(r[3]) : "r"(addr));
}
__device__ __forceinline__ void ldmA2(uint32_t* r, uint32_t addr) {
    asm volatile("ldmatrix.sync.aligned.m8n8.x2.shared.b16 {%0,%1}, [%2];"
                 : "=r"(r[0]), "=r"(r[1]) : "r"(addr));
}
__device__ __forceinline__ void ldmBT(uint32_t* r, uint32_t addr) {
    asm volatile("ldmatrix.sync.aligned.m8n8.x2.trans.shared.b16 {%0,%1}, [%2];"
                 : "=r"(r[0]), "=r"(r[1]) : "r"(addr));
}
__device__ __forceinline__ void mma_bf16(float* c, const uint32_t* a, const uint32_t* b) {
    asm volatile("mma.sync.aligned.m16n8k16.row.col.f32.bf16.bf16.f32 "
                 "{%0,%1,%2,%3}, {%4,%5,%6,%7}, {%8,%9}, {%0,%1,%2,%3};"
                 : "+f"(c[0]), "+f"(c[1]), "+f"(c[2]), "+f"(c[3])
                 : "r"(a[0]), "r"(a[1]), "r"(a[2]), "r"(a[3]), "r"(b[0]), "r"(b[1]));
}
#define CP16(dst, src) \
    asm volatile("cp.async.ca.shared.global [%0], [%1], 16;" :: "r"(dst), "l"(src))
#define CP_COMMIT() asm volatile("cp.async.commit_group;")
#define CP_WAIT(n)  asm volatile("cp.async.wait_group %0;" :: "n"(n))

// ---------------- one-shot fp32 -> bf16 hi/lo conversion ----------------
__global__ __launch_bounds__(256) void convert_kernel(const float* __restrict__ x,
                                                      const float* __restrict__ W1) {
    const size_t NX4 = (size_t)NN * KIN / 4;
    const size_t NW4 = (size_t)KIN * HO / 4;
    size_t i = (size_t)blockIdx.x * 256 + threadIdx.x;
    if (i < NX4) {
        float4 v = ((const float4*)x)[i];
        float lx, ly, lz, lw;
        uint2 hi = make_uint2(pkbf(v.x, v.y, &lx, &ly), pkbf(v.z, v.w, &lz, &lw));
        uint2 lo = make_uint2(pkbf2(lx, ly), pkbf2(lz, lw));
        ((uint2*)g_xh)[i] = hi;
        ((uint2*)g_xl)[i] = lo;
    } else if (i < NX4 + NW4) {
        size_t j = i - NX4;
        float4 v = ((const float4*)W1)[j];
        float lx, ly, lz, lw;
        uint2 hi = make_uint2(pkbf(v.x, v.y, &lx, &ly), pkbf(v.z, v.w, &lz, &lw));
        uint2 lo = make_uint2(pkbf2(lx, ly), pkbf2(lz, lw));
        ((uint2*)g_w1h)[j] = hi;
        ((uint2*)g_w1l)[j] = lo;
    }
}

// ---------------- GEMM1 via mma.sync bf16 split (3-MMA), cp.async double-buffered ----------------
#define BK    32
#define ASTR  40
#define BSTR  136
#define A_BYTES (128 * ASTR * 2)
#define B_BYTES (BK * BSTR * 2)
#define STG_BYTES (2 * A_BYTES + 2 * B_BYTES)
#define OFF_AH 0
#define OFF_AL A_BYTES
#define OFF_BH (2 * A_BYTES)
#define OFF_BL (2 * A_BYTES + B_BYTES)
#define GEMM1_SMEM (2 * STG_BYTES)

__global__ __launch_bounds__(256, 2) void gemm1_mma_kernel() {
    extern __shared__ __align__(16) char sm[];
    uint32_t sbase = smem_u32(sm);

    int tid = threadIdx.x, lane = tid & 31, wid = tid >> 5;
    int bm = blockIdx.y * 128, bn = blockIdx.x * 128;
    int wm = (wid >> 1) * 32, wn = (wid & 1) * 64;

    float acc[2][8][4];
#pragma unroll
    for (int i = 0; i < 2; i++)
#pragma unroll
        for (int j = 0; j < 8; j++)
#pragma unroll
            for (int q = 0; q < 4; q++) acc[i][j][q] = 0.f;

    int ar0 = tid >> 2, aj0 = tid & 3;
    int ar1 = (tid + 256) >> 2, aj1 = aj0;
    int gr0 = bm + ar0; if (gr0 >= NN) gr0 = NN - 1;
    int gr1 = bm + ar1; if (gr1 >= NN) gr1 = NN - 1;
    const unsigned short* axh0 = g_xh + (size_t)gr0 * KIN + aj0 * 8;
    const unsigned short* axh1 = g_xh + (size_t)gr1 * KIN + aj1 * 8;
    const unsigned short* axl0 = g_xl + (size_t)gr0 * KIN + aj0 * 8;
    const unsigned short* axl1 = g_xl + (size_t)gr1 * KIN + aj1 * 8;
    uint32_t adst0 = ar0 * (ASTR * 2) + aj0 * 16;
    uint32_t adst1 = ar1 * (ASTR * 2) + aj1 * 16;

    int bk0 = tid >> 4, bj0 = tid & 15;
    int bk1 = (tid + 256) >> 4, bj1 = bj0;
    const unsigned short* bwh0 = g_w1h + (size_t)bk0 * HO + bn + bj0 * 8;
    const unsigned short* bwh1 = g_w1h + (size_t)bk1 * HO + bn + bj1 * 8;
    const unsigned short* bwl0 = g_w1l + (size_t)bk0 * HO + bn + bj0 * 8;
    const unsigned short* bwl1 = g_w1l + (size_t)bk1 * HO + bn + bj1 * 8;
    uint32_t bdst0 = bk0 * (BSTR * 2) + bj0 * 16;
    uint32_t bdst1 = bk1 * (BSTR * 2) + bj1 * 16;

    auto load_stage = [&](int s, int c0) {
        uint32_t sb = sbase + s * STG_BYTES;
        CP16(sb + OFF_AH + adst0, axh0 + c0);
        CP16(sb + OFF_AH + adst1, axh1 + c0);
        CP16(sb + OFF_AL + adst0, axl0 + c0);
        CP16(sb + OFF_AL + adst1, axl1 + c0);
        CP16(sb + OFF_BH + bdst0, bwh0 + (size_t)c0 * HO);
        CP16(sb + OFF_BH + bdst1, bwh1 + (size_t)c0 * HO);
        CP16(sb + OFF_BL + bdst0, bwl0 + (size_t)c0 * HO);
        CP16(sb + OFF_BL + bdst1, bwl1 + (size_t)c0 * HO);
    };

    int aRow = (lane & 15);
    int aColB = (lane >> 4) << 4;
    int bK = (lane & 15);

    load_stage(0, 0);
    CP_COMMIT();

    for (int it = 0; it < KIN / BK; it++) {
        if (it + 1 < KIN / BK) {
            load_stage((it + 1) & 1, (it + 1) * BK);
            CP_COMMIT();
            CP_WAIT(1);
        } else {
            CP_WAIT(0);
        }
        __syncthreads();

        uint32_t sb = sbase + (it & 1) * STG_BYTES;
        uint32_t aH = sb + OFF_AH, aL = sb + OFF_AL;
        uint32_t bH = sb + OFF_BH, bL = sb + OFF_BL;

#pragma unroll
        for (int kk = 0; kk < BK; kk += 16) {
            uint32_t afh[2][4], afl[2][4];
#pragma unroll
            for (int mf = 0; mf < 2; mf++) {
                uint32_t aoff = (uint32_t)((wm + mf * 16 + aRow) * ASTR + kk) * 2 + aColB;
                ldmA(afh[mf], aH + aoff);
                ldmA(afl[mf], aL + aoff);
            }
#pragma unroll
            for (int nf = 0; nf < 8; nf++) {
                uint32_t bfh[2], bfl[2];
                uint32_t boff = (uint32_t)((kk + bK) * BSTR + wn + nf * 8) * 2;
                ldmBT(bfh, bH + boff);
                ldmBT(bfl, bL + boff);
#pragma unroll
                for (int mf = 0; mf < 2; mf++) {
                    mma_bf16(acc[mf][nf], afh[mf], bfh);
                    mma_bf16(acc[mf][nf], afl[mf], bfh);
                    mma_bf16(acc[mf][nf], afh[mf], bfl);
                }
            }
        }
        __syncthreads();
    }

    int rBase = bm + wm + (lane >> 2);
    int cBase = bn + wn + (lane & 3) * 2;
#pragma unroll
    for (int mf = 0; mf < 2; mf++) {
#pragma unroll
        for (int nf = 0; nf < 8; nf++) {
            int r0 = rBase + mf * 16;
            int col = cBase + nf * 8;
            if (r0 < NN)
                *(float2*)&g_h1[(size_t)r0 * HO + col] = make_float2(acc[mf][nf][0], acc[mf][nf][1]);
            if (r0 + 8 < NN)
                *(float2*)&g_h1[(size_t)(r0 + 8) * HO + col] = make_float2(acc[mf][nf][2], acc[mf][nf][3]);
        }
    }
}

// ---------------- per-node attention scores ----------------
__global__ __launch_bounds__(256) void scores1_kernel(const float* __restrict__ a_src,
                                                      const float* __restrict__ a_dst) {
    int w = (blockIdx.x * 256 + threadIdx.x) >> 5;
    int lane = threadIdx.x & 31;
    if (w >= NN) return;

    float ss[NH], dd[NH];
#pragma unroll
    for (int h = 0; h < NH; h++) {
        float v = g_h1[(size_t)w * HO + h * 32 + lane];
        ss[h] = v * a_src[h * 32 + lane];
        dd[h] = v * a_dst[h * 32 + lane];
    }
#pragma unroll
    for (int o = 16; o > 0; o >>= 1) {
#pragma unroll
        for (int h = 0; h < NH; h++) {
            ss[h] += __shfl_xor_sync(0xffffffffu, ss[h], o);
            dd[h] += __shfl_xor_sync(0xffffffffu, dd[h], o);
        }
    }
    if (lane == 0) {
#pragma unroll
        for (int h = 0; h < NH; h++) {
            g_es1[w * NH + h] = ss[h];
            g_ed1[w * NH + h] = dd[h];
        }
    }
}

// ---------------- CSR build ----------------
__global__ void zero_kernel() {
    int i = blockIdx.x * blockDim.x + threadIdx.x;
    if (i < NN) { g_deg[i] = 0; g_cursor[i] = 0; }
}

__global__ void hist_kernel(const int* __restrict__ dst) {
    int i = blockIdx.x * blockDim.x + threadIdx.x;
    if (i < EE) atomicAdd(&g_deg[dst[i]], 1);
}

__global__ __launch_bounds__(1024) void scan1_kernel() {
    __shared__ int wsum[32];
    int tid = threadIdx.x, lane = tid & 31, wid = tid >> 5;
    int i = blockIdx.x * 1024 + tid;
    int v = (i < NN) ? g_deg[i] : 0;
    int x = v;
#pragma unroll
    for (int o = 1; o < 32; o <<= 1) {
        int y = __shfl_up_sync(0xffffffffu, x, o);
        if (lane >= o) x += y;
    }
    if (lane == 31) wsum[wid] = x;
    __syncthreads();
    if (wid == 0) {
        int s = wsum[lane];
#pragma unroll
        for (int o = 1; o < 32; o <<= 1) {
            int y = __shfl_up_sync(0xffffffffu, s, o);
            if (lane >= o) s += y;
        }
        wsum[lane] = s;
    }
    __syncthreads();
    int incl = x + (wid ? wsum[wid - 1] : 0);
    if (i < NN) g_rowptr[i + 1] = incl;
    if (tid == 1023) g_bsum[blockIdx.x] = incl;
}

__global__ void scan2_kernel() {
    __shared__ int wtot;
    int tid = threadIdx.x, lane = tid & 31, wid = tid >> 5;
    int v = (tid < 49) ? g_bsum[tid] : 0;
    int x = v;
#pragma unroll
    for (int o = 1; o < 32; o <<= 1) {
        int y = __shfl_up_sync(0xffffffffu, x, o);
        if (lane >= o) x += y;
    }
    if (wid == 0 && lane == 31) wtot = x;
    __syncthreads();
    int incl = x + (wid ? wtot : 0);
    if (tid < 49) g_bsum[tid] = incl - v;
}

__global__ __launch_bounds__(1024) void scan3_kernel() {
    int tid = threadIdx.x;
    int i = blockIdx.x * 1024 + tid;
    int off = g_bsum[blockIdx.x];
    if (i < NN) g_rowptr[i + 1] += off;
    if (blockIdx.x == 0 && tid == 0) g_rowptr[0] = 0;
}

__global__ void scatter_kernel(const int* __restrict__ src, const int* __restrict__ dst) {
    int i = blockIdx.x * blockDim.x + threadIdx.x;
    if (i < EE) {
        int d = dst[i];
        int pos = atomicAdd(&g_cursor[d], 1);
        g_csrsrc[g_rowptr[d] + pos] = src[i];
    }
}

// ---------------- layer-1 aggregation: lane-parallel exp, chunked (32 edges/warp) ----------------
__global__ __launch_bounds__(256) void agg1_kernel() {
    __shared__ float psm[8][32][8];
    int tid = threadIdx.x;
    int wl = tid >> 5;
    int w = (blockIdx.x * 256 + tid) >> 5;
    int lane = tid & 31;
    if (w >= NN) return;

    int beg = g_rowptr[w], end = g_rowptr[w + 1];

    float4 e0 = *(const float4*)&g_ed1[w * NH];
    float4 e1 = *(const float4*)&g_ed1[w * NH + 4];
    float edv[NH] = {e0.x, e0.y, e0.z, e0.w, e1.x, e1.y, e1.z, e1.w};

    float ssum[NH], acc[NH];
#pragma unroll
    for (int h = 0; h < NH; h++) { ssum[h] = 0.f; acc[h] = 0.f; }

    for (int base = beg; base < end; base += 32) {
        int cnt = end - base; if (cnt > 32) cnt = 32;
        int s = 0;
        if (lane < cnt) {
            s = g_csrsrc[base + lane];
            float4 s0 = *(const float4*)&g_es1[s * NH];
            float4 s1 = *(const float4*)&g_es1[s * NH + 4];
            float sv[NH] = {s0.x, s0.y, s0.z, s0.w, s1.x, s1.y, s1.z, s1.w};
            float pv[NH];
#pragma unroll
            for (int h = 0; h < NH; h++) {
                float l = sv[h] + edv[h];
                l = l > 0.f ? l : 0.2f * l;
                pv[h] = __expf(l);
            }
            *(float4*)&psm[wl][lane][0] = make_float4(pv[0], pv[1], pv[2], pv[3]);
            *(float4*)&psm[wl][lane][4] = make_float4(pv[4], pv[5], pv[6], pv[7]);
        }
        __syncwarp();
        for (int j = 0; j < cnt; j++) {
            int sj = __shfl_sync(0xffffffffu, s, j);
            float4 p0 = *(const float4*)&psm[wl][j][0];
            float4 p1 = *(const float4*)&psm[wl][j][4];
            float pj[NH] = {p0.x, p0.y, p0.z, p0.w, p1.x, p1.y, p1.z, p1.w};
            const float* hp = &g_h1[(size_t)sj * HO + lane];
#pragma unroll
            for (int h = 0; h < NH; h++) {
                ssum[h] += pj[h];
                acc[h] = fmaf(pj[h], hp[h * 32], acc[h]);
            }
        }
        __syncwarp();
    }

    float* op = &g_out1[(size_t)w * HO + lane];
#pragma unroll
    for (int h = 0; h < NH; h++) {
        float d = ssum[h] > 0.f ? ssum[h] : 1.f;
        float v = acc[h] / d;
        v = v > 0.f ? v : (__expf(v) - 1.f);   // ELU
        op[h * 32] = v;
    }
}

// ---------------- GEMM2 via mma.sync bf16 split + fused es2/ed2 scores ----------------
// CTA: 128 rows x 16 cols, K=256 in BK=32 chunks, in-kernel fp32->bf16 conversion.
#define G2_ASTR 40
#define G2_BSTR 136

__global__ __launch_bounds__(256) void gemm2_mma_kernel(const float* __restrict__ W2,
                                                        const float* __restrict__ a2s,
                                                        const float* __restrict__ a2d) {
    __shared__ __align__(16) uint16_t Ah2[128 * G2_ASTR];
    __shared__ __align__(16) uint16_t Al2[128 * G2_ASTR];
    __shared__ __align__(16) uint16_t Bh2[BK * G2_BSTR];
    __shared__ __align__(16) uint16_t Bl2[BK * G2_BSTR];
    __shared__ float a2sv[CC], a2dv[CC];

    int tid = threadIdx.x, lane = tid & 31, wid = tid >> 5;
    int bm = blockIdx.x * 128;
    if (tid < CC) { a2sv[tid] = a2s[tid]; a2dv[tid] = a2d[tid]; }

    uint32_t aH = smem_u32(Ah2), aL = smem_u32(Al2);
    uint32_t bH = smem_u32(Bh2), bL = smem_u32(Bl2);

    float acc[2][4];
#pragma unroll
    for (int i = 0; i < 2; i++)
#pragma unroll
        for (int q = 0; q < 4; q++) acc[i][q] = 0.f;

    int aRow = (lane & 15);
    int aColB = (lane >> 4) << 4;
    int bK = (lane & 15);
    int wm = wid * 16;

    // A staging map: 1024 float4 chunks (128 rows x 8), threads do 4 each
    int arow = tid >> 1;                 // 0..127 (two threads per row)
    int ajh = (tid & 1) * 4;             // float4 index 0..3 / 4..7
    int garow = bm + arow; if (garow >= NN) garow = NN - 1;
    const float4* arp = (const float4*)(g_out1 + (size_t)garow * HO) + ajh;

    for (int k0 = 0; k0 < HO; k0 += BK) {
        // stage A [128 x 32] with inline conversion
        int kq = k0 / 4;
#pragma unroll
        for (int j = 0; j < 4; j++) {
            float4 v = arp[kq + j];
            float lx, ly, lz, lw;
            uint32_t h01 = pkbf(v.x, v.y, &lx, &ly);
            uint32_t h23 = pkbf(v.z, v.w, &lz, &lw);
            int idx = arow * G2_ASTR + (ajh + j) * 4;
            *(uint32_t*)&Ah2[idx]     = h01;
            *(uint32_t*)&Ah2[idx + 2] = h23;
            *(uint32_t*)&Al2[idx]     = pkbf2(lx, ly);
            *(uint32_t*)&Al2[idx + 2] = pkbf2(lz, lw);
        }
        // stage B [32 x 16]: 512 elems, 2 per thread
#pragma unroll
        for (int t = 0; t < 2; t++) {
            int idx = tid + t * 256;
            int kk = idx >> 4, c = idx & 15;
            float b = W2[(size_t)(k0 + kk) * CC + c];
            float lo;
            uint32_t hp;
            {
                __nv_bfloat16 hb = __float2bfloat16(b);
                lo = b - __bfloat162float(hb);
                hp = (uint32_t)__bfloat16_as_ushort(hb);
            }
            Bh2[kk * G2_BSTR + c] = (uint16_t)hp;
            Bl2[kk * G2_BSTR + c] = (uint16_t)__bfloat16_as_ushort(__float2bfloat16(lo));
        }
        __syncthreads();

#pragma unroll
        for (int kk = 0; kk < BK; kk += 16) {
            uint32_t afh[4], afl[4];
            uint32_t aoff = (uint32_t)((wm + aRow) * G2_ASTR + kk) * 2 + aColB;
            ldmA(afh, aH + aoff);
            ldmA(afl, aL + aoff);
#pragma unroll
            for (int nf = 0; nf < 2; nf++) {
                uint32_t bfh[2], bfl[2];
                uint32_t boff = (uint32_t)((kk + bK) * G2_BSTR + nf * 8) * 2;
                ldmBT(bfh, bH + boff);
                ldmBT(bfl, bL + boff);
                mma_bf16(acc[nf], afh, bfh);
                mma_bf16(acc[nf], afl, bfh);
                mma_bf16(acc[nf], afh, bfl);
            }
        }
        __syncthreads();
    }

    // epilogue: write h2 + fused scores
    int r0 = bm + wm + (lane >> 2);
    int c0 = (lane & 3) * 2;
    float sp0 = 0.f, dp0 = 0.f, sp1 = 0.f, dp1 = 0.f;
#pragma unroll
    for (int nf = 0; nf < 2; nf++) {
        int col = c0 + nf * 8;
        if (r0 < NN)
            *(float2*)&g_h2[(size_t)r0 * CC + col] = make_float2(acc[nf][0], acc[nf][1]);
        if (r0 + 8 < NN)
            *(float2*)&g_h2[(size_t)(r0 + 8) * CC + col] = make_float2(acc[nf][2], acc[nf][3]);
        sp0 = fmaf(acc[nf][0], a2sv[col], fmaf(acc[nf][1], a2sv[col + 1], sp0));
        dp0 = fmaf(acc[nf][0], a2dv[col], fmaf(acc[nf][1], a2dv[col + 1], dp0));
        sp1 = fmaf(acc[nf][2], a2sv[col], fmaf(acc[nf][3], a2sv[col + 1], sp1));
        dp1 = fmaf(acc[nf][2], a2dv[col], fmaf(acc[nf][3], a2dv[col + 1], dp1));
    }
#pragma unroll
    for (int o = 1; o < 4; o <<= 1) {
        sp0 += __shfl_xor_sync(0xffffffffu, sp0, o);
        dp0 += __shfl_xor_sync(0xffffffffu, dp0, o);
        sp1 += __shfl_xor_sync(0xffffffffu, sp1, o);
        dp1 += __shfl_xor_sync(0xffffffffu, dp1, o);
    }
    if ((lane & 3) == 0) {
        if (r0 < NN)     { g_es2[r0]     = sp0; g_ed2[r0]     = dp0; }
        if (r0 + 8 < NN) { g_es2[r0 + 8] = sp1; g_ed2[r0 + 8] = dp1; }
    }
}

// ---------------- layer-2 aggregation: lane-parallel exp, chunked + log_softmax ----------------
__global__ __launch_bounds__(256) void agg2_kernel(float* __restrict__ outp) {
    int tid = threadIdx.x;
    int w = (blockIdx.x * 256 + tid) >> 5;
    int lane = tid & 31;
    if (w >= NN) return;

    int beg = g_rowptr[w], end = g_rowptr[w + 1];
    float edv = g_ed2[w];

    int c = lane & 15;
    float ssum = 0.f, acc = 0.f;

    for (int base = beg; base < end; base += 32) {
        int cnt = end - base; if (cnt > 32) cnt = 32;
        int s = 0; float p = 0.f;
        if (lane < cnt) {
            s = g_csrsrc[base + lane];
            float l = g_es2[s] + edv;
            l = l > 0.f ? l : 0.2f * l;
            p = __expf(l);
        }
        for (int j = 0; j < cnt; j++) {
            int sj = __shfl_sync(0xffffffffu, s, j);
            float pj = __shfl_sync(0xffffffffu, p, j);
            ssum += pj;
            acc = fmaf(pj, g_h2[(size_t)sj * CC + c], acc);
        }
    }
    float d = ssum > 0.f ? ssum : 1.f;
    float v = acc / d;

    float mx = v;
#pragma unroll
    for (int o = 8; o > 0; o >>= 1)
        mx = fmaxf(mx, __shfl_xor_sync(0xffffffffu, mx, o));
    float se = __expf(v - mx);
#pragma unroll
    for (int o = 8; o > 0; o >>= 1)
        se += __shfl_xor_sync(0xffffffffu, se, o);
    float res = v - mx - __logf(se);

    if (lane < 16) outp[(size_t)w * CC + lane] = res;
}

// ---------------- launch ----------------
extern "C" void kernel_launch(void* const* d_in, const int* in_sizes, int n_in,
                              void* d_out, int out_size) {
    const float* x   = (const float*)d_in[0];
    const float* W1  = (const float*)d_in[1];
    const float* a1s = (const float*)d_in[2];
    const float* a1d = (const float*)d_in[3];
    const float* W2  = (const float*)d_in[4];
    const float* a2s = (const float*)d_in[5];
    const float* a2d = (const float*)d_in[6];
    const int*   ei  = (const int*)d_in[7];
    float* out = (float*)d_out;

    cudaFuncSetAttribute(gemm1_mma_kernel, cudaFuncAttributeMaxDynamicSharedMemorySize, GEMM1_SMEM);

    const size_t NCV = ((size_t)NN * KIN / 4 + (size_t)KIN * HO / 4 + 255) / 256;
    convert_kernel<<<(unsigned)NCV, 256>>>(x, W1);

    gemm1_mma_kernel<<<dim3(2, 391), 256, GEMM1_SMEM>>>();

    scores1_kernel<<<6250, 256>>>(a1s, a1d);

    zero_kernel<<<(NN + 255) / 256, 256>>>();
    hist_kernel<<<(EE + 255) / 256, 256>>>(ei + EE);
    scan1_kernel<<<49, 1024>>>();
    scan2_kernel<<<1, 64>>>();
    scan3_kernel<<<49, 1024>>>();
    scatter_kernel<<<(EE + 255) / 256, 256>>>(ei, ei + EE);

    agg1_kernel<<<6250, 256>>>();

    gemm2_mma_kernel<<<391, 256>>>(W2, a2s, a2d);

    agg2_kernel<<<6250, 256>>>(out);
}